// round 3
// baseline (speedup 1.0000x reference)
#include <cuda_runtime.h>
#include <math.h>

// Problem constants (fixed shapes from reference setup_inputs)
#define BB 8
#define FF 64
#define TT 2048
#define NROW (BB * FF)          // 512 (b,f) rows
#define GRID 128                // 128 blocks, 4 warps each -> 1 warp per row
#define NTHR 128

#define ALPHA_MIN 0.08f
#define ALPHA_MAX 0.45f
#define BETA      0.12f
#define SIG_SLOPE 8.0f
#define SIG_OFFSET 1.5f
#define EPSV      1e-12f

// Scratch: per-(b,f) sqrt(plv + eps); plus completion counter.
__device__ float        g_scratch[NROW];
__device__ unsigned int g_counter = 0;

__global__ __launch_bounds__(NTHR)
void amch_kernel(const float* __restrict__ phases,
                 const float* __restrict__ prev_coh,
                 const float* __restrict__ prev_alpha,
                 float* __restrict__ out)
{
    const int tid  = threadIdx.x;
    const int w    = tid >> 5;
    const int lane = tid & 31;
    const int row  = blockIdx.x * 4 + w;      // one warp owns one (b,f) row

    // ---- warp-private reduction of cos/sin over T = 2048 ----
    // 64 elems/lane = 16 x float4, fully unrolled -> ptxas front-batches loads
    // (high MLP), DRAM latency overlapped with MUFU work.
    const float4* p4 = (const float4*)(phases + (size_t)row * TT);
    float sc = 0.f, ss = 0.f;
#pragma unroll
    for (int i = 0; i < 16; ++i) {
        float4 v = p4[lane + i * 32];
        ss += __sinf(v.x); sc += __cosf(v.x);
        ss += __sinf(v.y); sc += __cosf(v.y);
        ss += __sinf(v.z); sc += __cosf(v.z);
        ss += __sinf(v.w); sc += __cosf(v.w);
    }
#pragma unroll
    for (int o = 16; o > 0; o >>= 1) {
        sc += __shfl_xor_sync(0xFFFFFFFFu, sc, o);
        ss += __shfl_xor_sync(0xFFFFFFFFu, ss, o);
    }

    __shared__ float s_last;
    if (lane == 0) {
        float mc = sc * (1.0f / TT);
        float ms = ss * (1.0f / TT);
        float plv = sqrtf(mc * mc + ms * ms);
        g_scratch[row] = sqrtf(plv + EPSV);
    }
    __syncthreads();

    if (tid == 0) {
        __threadfence();                      // publish scratch before counting
        unsigned t = atomicAdd(&g_counter, 1u);
        s_last = (t == (unsigned)(GRID - 1)) ? 1.f : 0.f;
    }
    __syncthreads();

    // ---- the single last-finishing block does the tiny epilogue ----
    if (s_last != 0.f) {
        // 4 warps; warp w handles batches {w, w+4}: 64 scratch values each.
#pragma unroll
        for (int b = w; b < BB; b += 4) {
            float v2 = __ldcg(&g_scratch[b * FF + lane]) +
                       __ldcg(&g_scratch[b * FF + 32 + lane]);
#pragma unroll
            for (int o = 16; o > 0; o >>= 1) v2 += __shfl_xor_sync(0xFFFFFFFFu, v2, o);
            if (lane == 0) {
                float coh = v2 * (1.0f / FF);
                coh = fminf(fmaxf(coh, 0.0f), 1.0f);
                float pc = prev_coh[b];
                float pa = prev_alpha[b];
                float vel = fabsf(coh - pc);
                float x = SIG_SLOPE * vel - SIG_OFFSET;
                float sig = 1.0f / (1.0f + __expf(-x));
                float target = ALPHA_MIN + (ALPHA_MAX - ALPHA_MIN) * sig;
                float alpha = pa + BETA * (target - pa);
                out[b] = alpha * coh + (1.0f - alpha) * pc;
            }
        }
        if (tid == 0) g_counter = 0;          // reset for next graph replay
    }
}

extern "C" void kernel_launch(void* const* d_in, const int* in_sizes, int n_in,
                              void* d_out, int out_size)
{
    const float* phases     = (const float*)d_in[0];   // [8, 64, 2048] f32
    const float* prev_coh   = (const float*)d_in[1];   // [8] f32
    const float* prev_alpha = (const float*)d_in[2];   // [8] f32
    float* out = (float*)d_out;                        // [8] f32

    amch_kernel<<<GRID, NTHR>>>(phases, prev_coh, prev_alpha, out);
}

// round 4
// speedup vs baseline: 1.3430x; 1.3430x over previous
#include <cuda_runtime.h>
#include <math.h>

// Problem constants (fixed shapes from reference setup_inputs)
#define BB 8
#define FF 64
#define TT 2048
#define NROW (BB * FF)          // 512 rows, one CTA each
#define NTHR 128

#define ALPHA_MIN 0.08f
#define ALPHA_MAX 0.45f
#define BETA      0.12f
#define SIG_SLOPE 8.0f
#define SIG_OFFSET 1.5f
#define EPSV      1e-12f

#define FIX_SCALE 16777216.0f   // 2^24 fixed point for sqrt values in [0,1]

// One 64-bit accumulator per batch b, strided 256B so the 8 addresses land on
// different L2 slices. Top byte = arrival count, low 56 bits = fixed-point sum.
__device__ unsigned long long g_accum[BB * 32];   // index b*32

__global__ __launch_bounds__(NTHR)
void amch_kernel(const float* __restrict__ phases,
                 const float* __restrict__ prev_coh,
                 const float* __restrict__ prev_alpha,
                 float* __restrict__ out)
{
    const int tid  = threadIdx.x;
    const int w    = tid >> 5;
    const int lane = tid & 31;
    const int row  = blockIdx.x;          // flat (b*F + f)
    const int b    = row >> 6;

    // ---- per-row reduction of cos/sin over T = 2048 (16 elems/thread) ----
    const float4* p4 = (const float4*)(phases + (size_t)row * TT);
    float4 v[4];
#pragma unroll
    for (int i = 0; i < 4; ++i) v[i] = p4[tid + i * NTHR];

    float sc = 0.f, ss = 0.f;
#pragma unroll
    for (int i = 0; i < 4; ++i) {
        ss += __sinf(v[i].x); sc += __cosf(v[i].x);
        ss += __sinf(v[i].y); sc += __cosf(v[i].y);
        ss += __sinf(v[i].z); sc += __cosf(v[i].z);
        ss += __sinf(v[i].w); sc += __cosf(v[i].w);
    }
#pragma unroll
    for (int o = 16; o > 0; o >>= 1) {
        sc += __shfl_xor_sync(0xFFFFFFFFu, sc, o);
        ss += __shfl_xor_sync(0xFFFFFFFFu, ss, o);
    }

    __shared__ float smc[4], sms[4];
    if (lane == 0) { smc[w] = sc; sms[w] = ss; }
    __syncthreads();

    if (tid == 0) {
        float mc = (smc[0] + smc[1] + smc[2] + smc[3]) * (1.0f / TT);
        float ms = (sms[0] + sms[1] + sms[2] + sms[3]) * (1.0f / TT);
        float plv = sqrtf(mc * mc + ms * ms);
        float val = sqrtf(plv + EPSV);              // in [0, ~1]

        // Fused count+sum atomic: top byte counts arrivals, low bits sum.
        unsigned fx = (unsigned)(val * FIX_SCALE + 0.5f);
        unsigned long long inc = (1ULL << 56) | (unsigned long long)fx;
        unsigned long long old = atomicAdd(&g_accum[b * 32], inc);

        if ((old >> 56) == (unsigned long long)(FF - 1)) {
            // We are the 64th (last) row of this batch: full sum in hand.
            unsigned long long tot = old + inc;
            float sum = (float)(tot & 0x00FFFFFFFFFFFFFFULL) * (1.0f / FIX_SCALE);
            float coh = sum * (1.0f / FF);
            coh = fminf(fmaxf(coh, 0.0f), 1.0f);
            float pc = prev_coh[b];
            float pa = prev_alpha[b];
            float vel = fabsf(coh - pc);
            float x = SIG_SLOPE * vel - SIG_OFFSET;
            float sig = 1.0f / (1.0f + __expf(-x));
            float target = ALPHA_MIN + (ALPHA_MAX - ALPHA_MIN) * sig;
            float alpha = pa + BETA * (target - pa);
            out[b] = alpha * coh + (1.0f - alpha) * pc;

            g_accum[b * 32] = 0ULL;   // reset for next graph replay
        }
    }
}

extern "C" void kernel_launch(void* const* d_in, const int* in_sizes, int n_in,
                              void* d_out, int out_size)
{
    const float* phases     = (const float*)d_in[0];   // [8, 64, 2048] f32
    const float* prev_coh   = (const float*)d_in[1];   // [8] f32
    const float* prev_alpha = (const float*)d_in[2];   // [8] f32
    float* out = (float*)d_out;                        // [8] f32

    amch_kernel<<<NROW, NTHR>>>(phases, prev_coh, prev_alpha, out);
}